// round 2
// baseline (speedup 1.0000x reference)
#include <cuda_runtime.h>
#include <cstdint>

#define NTOK  4096
#define HID   1024
#define NEXP  16
#define IDIM  2048
#define CAP   768
#define NFLAT (NTOK * 2)

// ---------------- device scratch (no allocs allowed) ----------------
__device__ int   g_flat_sel[NFLAT];
__device__ float g_flat_scale[NFLAT];
__device__ int   g_assign_pos[NFLAT];
__device__ int   g_expert_count[NEXP];
__device__ int   g_expert_tok[NEXP * CAP];
__device__ float g_xbuf[(size_t)NEXP * CAP * HID];        // gathered inputs   48MB
__device__ float g_hbuf[(size_t)NEXP * CAP * 2 * IDIM];   // gemm1 out        192MB
__device__ float g_ibuf[(size_t)NEXP * CAP * IDIM];       // activation        96MB
__device__ float g_ybuf[(size_t)NEXP * CAP * HID];        // gemm2 out         48MB

// ---------------- routing: softmax top-2 + capacity positions ----------------
__global__ void routing_kernel(const float* __restrict__ logits) {
    __shared__ unsigned char sh_sel[NFLAT];
    const int tid = threadIdx.x;  // 512 threads = 16 warps

    for (int t = tid; t < NTOK; t += 512) {
        const float* l = logits + t * NEXP;
        float l1 = -1e30f, l2 = -1e30f;
        int i1 = 0, i2 = 0;
#pragma unroll
        for (int j = 0; j < NEXP; j++) {
            float v = l[j];
            if (v > l1)      { l2 = l1; i2 = i1; l1 = v; i1 = j; }
            else if (v > l2) { l2 = v; i2 = j; }
        }
        // normalized top-2 softmax weights: s1 = e^{l1}/(e^{l1}+e^{l2})
        float e2 = __expf(l2 - l1);
        float s1 = 1.f / (1.f + e2);
        g_flat_sel[2 * t]     = i1;
        g_flat_sel[2 * t + 1] = i2;
        g_flat_scale[2 * t]     = s1;
        g_flat_scale[2 * t + 1] = 1.f - s1;
        sh_sel[2 * t]     = (unsigned char)i1;
        sh_sel[2 * t + 1] = (unsigned char)i2;
    }
    __syncthreads();

    // warp w owns expert w; scan flat order with ballot prefix
    const int w = tid >> 5, lane = tid & 31;
    int base = 0;
    for (int c = 0; c < NFLAT; c += 32) {
        int s = sh_sel[c + lane];
        unsigned m = __ballot_sync(0xffffffffu, s == w);
        if (s == w) {
            int pos = base + __popc(m & ((1u << lane) - 1u));
            g_assign_pos[c + lane] = (pos < CAP) ? pos : -1;
            if (pos < CAP) g_expert_tok[w * CAP + pos] = (c + lane) >> 1;
        }
        base += __popc(m);
    }
    if (lane == 0) g_expert_count[w] = base < CAP ? base : CAP;
}

// ---------------- gather rows into contiguous per-expert buffer ----------------
__global__ void gather_kernel(const float* __restrict__ hidden) {
    const int row = blockIdx.x;            // [0, NEXP*CAP)
    const int e = row / CAP, p = row % CAP;
    const int t = threadIdx.x;             // 256, one float4 each
    float4 v = make_float4(0.f, 0.f, 0.f, 0.f);
    if (p < g_expert_count[e]) {
        int tok = g_expert_tok[row];
        v = ((const float4*)(hidden + (size_t)tok * HID))[t];
    }
    ((float4*)(g_xbuf + (size_t)row * HID))[t] = v;
}

// ---------------- packed f32x2 FMA helpers ----------------
__device__ __forceinline__ unsigned long long dup2(float x) {
    unsigned long long r;
    unsigned u = __float_as_uint(x);
    asm("mov.b64 %0, {%1, %2};" : "=l"(r) : "r"(u), "r"(u));
    return r;
}
__device__ __forceinline__ void ffma2(unsigned long long& d,
                                      unsigned long long a, unsigned long long b) {
    asm("fma.rn.f32x2 %0, %1, %2, %0;" : "+l"(d) : "l"(a), "l"(b));
}

// ---------------- tiled SGEMM C = A * B^T (both K-major), per-expert ----------------
// A: [CAP, K] rows valid up to count[e]; B: [N, K]; C: [CAP, N]
template<int N, int K, bool FIRST>
__global__ __launch_bounds__(256, 2) void sgemm_kernel(const float* __restrict__ Bbase) {
    const int e = blockIdx.z;
    if ((int)(blockIdx.y * 128) >= g_expert_count[e]) return;

    const float* Abase = FIRST ? g_xbuf : g_ibuf;
    float*       Cbase = FIRST ? g_hbuf : g_ybuf;
    const float* A = Abase + (size_t)e * CAP * K + (size_t)blockIdx.y * 128 * K;
    const float* B = Bbase + (size_t)e * N * K + (size_t)blockIdx.x * 128 * K;
    float*       C = Cbase + (size_t)e * CAP * N + (size_t)blockIdx.y * 128 * N
                           + (size_t)blockIdx.x * 128;

    __shared__ float As[16][128];
    __shared__ float Bs[16][128];

    const int tid = threadIdx.x;
    const int tx = tid & 15, ty = tid >> 4;
    const int r0 = tid >> 2, c0 = tid & 3;   // load map: 2 float4 per operand

    const float* aPtr = A + (size_t)r0 * K + c0 * 4;
    const float* bPtr = B + (size_t)r0 * K + c0 * 4;

    unsigned long long acc[8][4];
#pragma unroll
    for (int i = 0; i < 8; i++)
#pragma unroll
        for (int j = 0; j < 4; j++) acc[i][j] = 0ull;

    for (int k0 = 0; k0 < K; k0 += 16) {
        float4 av0 = *(const float4*)(aPtr);
        float4 av1 = *(const float4*)(aPtr + (size_t)64 * K);
        float4 bv0 = *(const float4*)(bPtr);
        float4 bv1 = *(const float4*)(bPtr + (size_t)64 * K);
        aPtr += 16; bPtr += 16;

        As[c0 * 4 + 0][r0] = av0.x; As[c0 * 4 + 1][r0] = av0.y;
        As[c0 * 4 + 2][r0] = av0.z; As[c0 * 4 + 3][r0] = av0.w;
        As[c0 * 4 + 0][r0 + 64] = av1.x; As[c0 * 4 + 1][r0 + 64] = av1.y;
        As[c0 * 4 + 2][r0 + 64] = av1.z; As[c0 * 4 + 3][r0 + 64] = av1.w;
        Bs[c0 * 4 + 0][r0] = bv0.x; Bs[c0 * 4 + 1][r0] = bv0.y;
        Bs[c0 * 4 + 2][r0] = bv0.z; Bs[c0 * 4 + 3][r0] = bv0.w;
        Bs[c0 * 4 + 0][r0 + 64] = bv1.x; Bs[c0 * 4 + 1][r0 + 64] = bv1.y;
        Bs[c0 * 4 + 2][r0 + 64] = bv1.z; Bs[c0 * 4 + 3][r0 + 64] = bv1.w;
        __syncthreads();

#pragma unroll
        for (int kk = 0; kk < 16; kk++) {
            float4 af0 = *(const float4*)&As[kk][ty * 8];
            float4 af1 = *(const float4*)&As[kk][ty * 8 + 4];
            ulonglong2 bq0 = *(const ulonglong2*)&Bs[kk][tx * 8];
            ulonglong2 bq1 = *(const ulonglong2*)&Bs[kk][tx * 8 + 4];
            unsigned long long aa[8] = {
                dup2(af0.x), dup2(af0.y), dup2(af0.z), dup2(af0.w),
                dup2(af1.x), dup2(af1.y), dup2(af1.z), dup2(af1.w)
            };
            unsigned long long bb[4] = { bq0.x, bq0.y, bq1.x, bq1.y };
#pragma unroll
            for (int i = 0; i < 8; i++)
#pragma unroll
                for (int j = 0; j < 4; j++)
                    ffma2(acc[i][j], aa[i], bb[j]);
        }
        __syncthreads();
    }

#pragma unroll
    for (int i = 0; i < 8; i++) {
        float* crow = C + (size_t)(ty * 8 + i) * N + tx * 8;
        float4 o0, o1;
        o0.x = __uint_as_float((unsigned)(acc[i][0]));
        o0.y = __uint_as_float((unsigned)(acc[i][0] >> 32));
        o0.z = __uint_as_float((unsigned)(acc[i][1]));
        o0.w = __uint_as_float((unsigned)(acc[i][1] >> 32));
        o1.x = __uint_as_float((unsigned)(acc[i][2]));
        o1.y = __uint_as_float((unsigned)(acc[i][2] >> 32));
        o1.z = __uint_as_float((unsigned)(acc[i][3]));
        o1.w = __uint_as_float((unsigned)(acc[i][3] >> 32));
        *(float4*)crow = o0;
        *(float4*)(crow + 4) = o1;
    }
}

// ---------------- activation: inter = g3 * silu(g1), g3=h[:, :I], g1=h[:, I:] ----------------
__global__ void act_kernel() {
    size_t idx4 = (size_t)blockIdx.x * 256 + threadIdx.x;   // float4 groups
    size_t row = idx4 >> 9;            // IDIM/4 = 512 groups per row
    int c4 = (int)(idx4 & 511);
    const float* hrow = g_hbuf + row * (2 * IDIM);
    float4 g3 = *(const float4*)(hrow + c4 * 4);
    float4 g1 = *(const float4*)(hrow + IDIM + c4 * 4);
    float4 o;
    o.x = g3.x * (g1.x / (1.f + __expf(-g1.x)));
    o.y = g3.y * (g1.y / (1.f + __expf(-g1.y)));
    o.z = g3.z * (g1.z / (1.f + __expf(-g1.z)));
    o.w = g3.w * (g1.w / (1.f + __expf(-g1.w)));
    *(float4*)(g_ibuf + row * IDIM + c4 * 4) = o;
}

// ---------------- scatter back: out[t] = sum_k scale * y[e, pos] ----------------
__global__ void scatter_kernel(float* __restrict__ out) {
    const int t = blockIdx.x;     // token
    const int tid = threadIdx.x;  // 256, one float4 each
    float4 acc = make_float4(0.f, 0.f, 0.f, 0.f);
#pragma unroll
    for (int k = 0; k < 2; k++) {
        int f = 2 * t + k;
        int pos = g_assign_pos[f];
        if (pos >= 0) {
            int e = g_flat_sel[f];
            float s = g_flat_scale[f];
            float4 v = ((const float4*)(g_ybuf + (size_t)(e * CAP + pos) * HID))[tid];
            acc.x += s * v.x; acc.y += s * v.y; acc.z += s * v.z; acc.w += s * v.w;
        }
    }
    ((float4*)(out + (size_t)t * HID))[tid] = acc;
}

// ---------------- launch ----------------
extern "C" void kernel_launch(void* const* d_in, const int* in_sizes, int n_in,
                              void* d_out, int out_size) {
    const float* hidden = (const float*)d_in[0];
    const float* logits = (const float*)d_in[1];
    const float* w31    = (const float*)d_in[2];
    const float* w2     = (const float*)d_in[3];
    float* out = (float*)d_out;

    routing_kernel<<<1, 512>>>(logits);
    gather_kernel<<<NEXP * CAP, 256>>>(hidden);
    sgemm_kernel<2 * IDIM, HID, true><<<dim3(32, 6, NEXP), 256>>>(w31);
    act_kernel<<<(NEXP * CAP * IDIM / 4) / 256, 256>>>();
    sgemm_kernel<HID, IDIM, false><<<dim3(8, 6, NEXP), 256>>>(w2);
    scatter_kernel<<<NTOK, 256>>>(out);
}

// round 7
// speedup vs baseline: 1.7999x; 1.7999x over previous
#include <cuda_runtime.h>
#include <cuda_bf16.h>
#include <cstdint>

#define NTOK  4096
#define HID   1024
#define NEXP  16
#define IDIM  2048
#define CAP   768
#define NFLAT (NTOK * 2)

// ---------------- device scratch (no allocs allowed) ----------------
__device__ int   g_flat_sel[NFLAT];
__device__ float g_flat_scale[NFLAT];
__device__ int   g_assign_pos[NFLAT];
__device__ int   g_expert_count[NEXP];
__device__ int   g_expert_tok[NEXP * CAP];

__device__ __align__(256) __nv_bfloat16 g_xh[(size_t)NEXP * CAP * HID];
__device__ __align__(256) __nv_bfloat16 g_xl[(size_t)NEXP * CAP * HID];
__device__ __align__(256) __nv_bfloat16 g_ih[(size_t)NEXP * CAP * IDIM];
__device__ __align__(256) __nv_bfloat16 g_il[(size_t)NEXP * CAP * IDIM];
__device__ __align__(256) __nv_bfloat16 g_w31h[(size_t)NEXP * 2 * IDIM * HID];
__device__ __align__(256) __nv_bfloat16 g_w31l[(size_t)NEXP * 2 * IDIM * HID];
__device__ __align__(256) __nv_bfloat16 g_w2h[(size_t)NEXP * HID * IDIM];
__device__ __align__(256) __nv_bfloat16 g_w2l[(size_t)NEXP * HID * IDIM];
__device__ __align__(256) float g_hbuf[(size_t)NEXP * CAP * 2 * IDIM];
__device__ __align__(256) float g_ybuf[(size_t)NEXP * CAP * HID];

// ---------------- helpers ----------------
__device__ __forceinline__ void mma16816(float* c, const uint32_t* a, const uint32_t* b) {
    asm volatile(
        "mma.sync.aligned.m16n8k16.row.col.f32.bf16.bf16.f32 "
        "{%0,%1,%2,%3}, {%4,%5,%6,%7}, {%8,%9}, {%0,%1,%2,%3};"
        : "+f"(c[0]), "+f"(c[1]), "+f"(c[2]), "+f"(c[3])
        : "r"(a[0]), "r"(a[1]), "r"(a[2]), "r"(a[3]), "r"(b[0]), "r"(b[1]));
}
__device__ __forceinline__ uint32_t pack2(__nv_bfloat16 a, __nv_bfloat16 b) {
    __nv_bfloat162 t(a, b);
    return *reinterpret_cast<uint32_t*>(&t);
}
// padded smem tile: 128 rows x 32 bf16 (64B data), row stride 80B -> conflict-free 4B lds
#define ROW_B 80
#define TILE_B (128 * ROW_B)          // 10240 bytes per operand tile

// ---------------- routing: softmax top-2 + capacity positions ----------------
__global__ void routing_kernel(const float* __restrict__ logits) {
    __shared__ unsigned char sh_sel[NFLAT];
    const int tid = threadIdx.x;  // 512 threads = 16 warps

    for (int t = tid; t < NTOK; t += 512) {
        const float* l = logits + t * NEXP;
        float l1 = -1e30f, l2 = -1e30f;
        int i1 = 0, i2 = 0;
#pragma unroll
        for (int j = 0; j < NEXP; j++) {
            float v = l[j];
            if (v > l1)      { l2 = l1; i2 = i1; l1 = v; i1 = j; }
            else if (v > l2) { l2 = v; i2 = j; }
        }
        float e2 = __expf(l2 - l1);
        float s1 = 1.f / (1.f + e2);
        g_flat_sel[2 * t]     = i1;
        g_flat_sel[2 * t + 1] = i2;
        g_flat_scale[2 * t]     = s1;
        g_flat_scale[2 * t + 1] = 1.f - s1;
        sh_sel[2 * t]     = (unsigned char)i1;
        sh_sel[2 * t + 1] = (unsigned char)i2;
    }
    __syncthreads();

    const int w = tid >> 5, lane = tid & 31;
    int base = 0;
    for (int c = 0; c < NFLAT; c += 32) {
        int s = sh_sel[c + lane];
        unsigned m = __ballot_sync(0xffffffffu, s == w);
        if (s == w) {
            int pos = base + __popc(m & ((1u << lane) - 1u));
            g_assign_pos[c + lane] = (pos < CAP) ? pos : -1;
            if (pos < CAP) g_expert_tok[w * CAP + pos] = (c + lane) >> 1;
        }
        base += __popc(m);
    }
    if (lane == 0) g_expert_count[w] = base < CAP ? base : CAP;
}

// ---------------- weight split: f32 -> bf16 hi + bf16 lo ----------------
// NOTE: destination __device__ arrays are resolved in DEVICE code (which flag);
// passing g_* symbols as kernel args from host was the R4-R6 context-killing bug.
__global__ void split_kernel(const float* __restrict__ src, int which, int n4) {
    __nv_bfloat16* hi = which ? g_w2h : g_w31h;
    __nv_bfloat16* lo = which ? g_w2l : g_w31l;
    int stride = gridDim.x * blockDim.x;
    for (int i = blockIdx.x * blockDim.x + threadIdx.x; i < n4; i += stride) {
        float4 v = ((const float4*)src)[i];
        __nv_bfloat16 h0 = __float2bfloat16_rn(v.x), h1 = __float2bfloat16_rn(v.y);
        __nv_bfloat16 h2 = __float2bfloat16_rn(v.z), h3 = __float2bfloat16_rn(v.w);
        ((uint2*)hi)[i] = make_uint2(pack2(h0, h1), pack2(h2, h3));
        ((uint2*)lo)[i] = make_uint2(
            pack2(__float2bfloat16_rn(v.x - __bfloat162float(h0)),
                  __float2bfloat16_rn(v.y - __bfloat162float(h1))),
            pack2(__float2bfloat16_rn(v.z - __bfloat162float(h2)),
                  __float2bfloat16_rn(v.w - __bfloat162float(h3))));
    }
}

// ---------------- gather rows into contiguous split-bf16 buffer ----------------
__global__ void gather_split(const float* __restrict__ hidden) {
    const int row = blockIdx.x;            // [0, NEXP*CAP)
    const int e = row / CAP, p = row % CAP;
    const int t = threadIdx.x;             // 256, one float4 each
    float4 v = make_float4(0.f, 0.f, 0.f, 0.f);
    if (p < g_expert_count[e]) {
        int tok = g_expert_tok[row];
        v = ((const float4*)(hidden + (size_t)tok * HID))[t];
    }
    __nv_bfloat16 h0 = __float2bfloat16_rn(v.x), h1 = __float2bfloat16_rn(v.y);
    __nv_bfloat16 h2 = __float2bfloat16_rn(v.z), h3 = __float2bfloat16_rn(v.w);
    *(uint2*)(g_xh + (size_t)row * HID + t * 4) = make_uint2(pack2(h0, h1), pack2(h2, h3));
    *(uint2*)(g_xl + (size_t)row * HID + t * 4) = make_uint2(
        pack2(__float2bfloat16_rn(v.x - __bfloat162float(h0)),
              __float2bfloat16_rn(v.y - __bfloat162float(h1))),
        pack2(__float2bfloat16_rn(v.z - __bfloat162float(h2)),
              __float2bfloat16_rn(v.w - __bfloat162float(h3))));
}

// ---------------- bf16 HMMA GEMM, virtual tripled-K, vanilla loads ----------------
// C[row][n] = Ah*Bh + Al*Bh + Ah*Bl  (fp32 emulation via 3 virtual K segments)
// CTA tile 128x128, BK=32 bf16, single smem buffer + register prefetch.
template<int NTOT, int K, bool FIRST>
__global__ __launch_bounds__(256, 2) void hmma_gemm() {
    const int e = blockIdx.z;
    if ((int)(blockIdx.y * 128) >= g_expert_count[e]) return;

    __shared__ __align__(16) char smA[TILE_B];
    __shared__ __align__(16) char smB[TILE_B];

    const size_t aoffg = ((size_t)e * CAP + (size_t)blockIdx.y * 128) * K;
    const __nv_bfloat16* Ah = (FIRST ? g_xh : g_ih) + aoffg;
    const __nv_bfloat16* Al = (FIRST ? g_xl : g_il) + aoffg;
    const size_t boffg = ((size_t)e * NTOT + (size_t)blockIdx.x * 128) * K;
    const __nv_bfloat16* Bh = (FIRST ? g_w31h : g_w2h) + boffg;
    const __nv_bfloat16* Bl = (FIRST ? g_w31l : g_w2l) + boffg;
    float* C = (FIRST ? g_hbuf : g_ybuf)
        + ((size_t)e * CAP + (size_t)blockIdx.y * 128) * NTOT + (size_t)blockIdx.x * 128;

    const int tid = threadIdx.x, lane = tid & 31, warp = tid >> 5;
    const int wm = (warp & 3) * 32, wn = (warp >> 2) * 64;

    // load map: each thread owns rows (tid>>2) and (tid>>2)+64, 16B chunk (tid&3)
    const int lrow0 = tid >> 2, lc0 = tid & 3;
    const int lrow1 = lrow0 + 64;
    const uint32_t s0 = (uint32_t)(lrow0 * ROW_B + lc0 * 16);
    const uint32_t s1 = (uint32_t)(lrow1 * ROW_B + lc0 * 16);
    const size_t ga0 = (size_t)lrow0 * K + lc0 * 8;
    const size_t ga1 = (size_t)lrow1 * K + lc0 * 8;

    float acc[2][8][4];
#pragma unroll
    for (int i = 0; i < 2; i++)
#pragma unroll
        for (int j = 0; j < 8; j++)
#pragma unroll
            for (int q = 0; q < 4; q++) acc[i][j][q] = 0.f;

    constexpr int NK = 3 * K / 32;

    uint4 rA0, rA1, rB0, rB1;
    auto gload = [&](int kt) {
        const int k0 = kt * 32;
        const __nv_bfloat16 *As, *Bs;
        int kl;
        if (k0 < K)          { As = Ah; Bs = Bh; kl = k0; }
        else if (k0 < 2 * K) { As = Al; Bs = Bh; kl = k0 - K; }
        else                 { As = Ah; Bs = Bl; kl = k0 - 2 * K; }
        rA0 = *(const uint4*)(As + ga0 + kl);
        rA1 = *(const uint4*)(As + ga1 + kl);
        rB0 = *(const uint4*)(Bs + ga0 + kl);
        rB1 = *(const uint4*)(Bs + ga1 + kl);
    };
    auto sstore = [&]() {
        *(uint4*)(smA + s0) = rA0;
        *(uint4*)(smA + s1) = rA1;
        *(uint4*)(smB + s0) = rB0;
        *(uint4*)(smB + s1) = rB1;
    };

    gload(0);
    sstore();

    const int mlo = lane >> 2;          // 0..7
    const int kp4 = (lane & 3) * 4;     // byte offset of k-pair

    for (int kt = 0; kt < NK; kt++) {
        __syncthreads();                // smem stores visible
        if (kt + 1 < NK) gload(kt + 1); // prefetch overlaps compute below

#pragma unroll
        for (int kk = 0; kk < 2; kk++) {
            const int kb = kk * 32;     // byte offset of k16-half within row
            uint32_t aF[2][4], bF[8][2];
#pragma unroll
            for (int i = 0; i < 2; i++) {
                const char* ab = smA + (wm + i * 16 + mlo) * ROW_B + kb + kp4;
                aF[i][0] = *(const uint32_t*)(ab);
                aF[i][1] = *(const uint32_t*)(ab + 8 * ROW_B);
                aF[i][2] = *(const uint32_t*)(ab + 16);
                aF[i][3] = *(const uint32_t*)(ab + 8 * ROW_B + 16);
            }
#pragma unroll
            for (int j = 0; j < 8; j++) {
                const char* bb = smB + (wn + j * 8 + mlo) * ROW_B + kb + kp4;
                bF[j][0] = *(const uint32_t*)(bb);
                bF[j][1] = *(const uint32_t*)(bb + 16);
            }
#pragma unroll
            for (int i = 0; i < 2; i++)
#pragma unroll
                for (int j = 0; j < 8; j++)
                    mma16816(acc[i][j], aF[i], bF[j]);
        }
        __syncthreads();                // all reads done
        if (kt + 1 < NK) sstore();
    }

    // epilogue: standard m16n8 C layout, f32 stores
    const int er = lane >> 2, ec = (lane & 3) * 2;
#pragma unroll
    for (int i = 0; i < 2; i++) {
#pragma unroll
        for (int j = 0; j < 8; j++) {
            float* p0 = C + (size_t)(wm + i * 16 + er) * NTOT + wn + j * 8 + ec;
            float* p1 = p0 + (size_t)8 * NTOT;
            *(float2*)p0 = make_float2(acc[i][j][0], acc[i][j][1]);
            *(float2*)p1 = make_float2(acc[i][j][2], acc[i][j][3]);
        }
    }
}

// ---------------- activation: inter = g3 * silu(g1), split to bf16 hi/lo ----------------
__global__ void act_kernel() {
    size_t idx4 = (size_t)blockIdx.x * 256 + threadIdx.x;   // float4 groups
    size_t row = idx4 >> 9;            // IDIM/4 = 512 groups per row
    int c4 = (int)(idx4 & 511);
    const float* hrow = g_hbuf + row * (2 * IDIM);
    float4 g3 = *(const float4*)(hrow + c4 * 4);
    float4 g1 = *(const float4*)(hrow + IDIM + c4 * 4);
    float4 o;
    o.x = g3.x * (g1.x / (1.f + __expf(-g1.x)));
    o.y = g3.y * (g1.y / (1.f + __expf(-g1.y)));
    o.z = g3.z * (g1.z / (1.f + __expf(-g1.z)));
    o.w = g3.w * (g1.w / (1.f + __expf(-g1.w)));
    __nv_bfloat16 h0 = __float2bfloat16_rn(o.x), h1 = __float2bfloat16_rn(o.y);
    __nv_bfloat16 h2 = __float2bfloat16_rn(o.z), h3 = __float2bfloat16_rn(o.w);
    *(uint2*)(g_ih + row * IDIM + c4 * 4) = make_uint2(pack2(h0, h1), pack2(h2, h3));
    *(uint2*)(g_il + row * IDIM + c4 * 4) = make_uint2(
        pack2(__float2bfloat16_rn(o.x - __bfloat162float(h0)),
              __float2bfloat16_rn(o.y - __bfloat162float(h1))),
        pack2(__float2bfloat16_rn(o.z - __bfloat162float(h2)),
              __float2bfloat16_rn(o.w - __bfloat162float(h3))));
}

// ---------------- scatter back: out[t] = sum_k scale * y[e, pos] ----------------
__global__ void scatter_kernel(float* __restrict__ out) {
    const int t = blockIdx.x;
    const int tid = threadIdx.x;  // 256, one float4 each
    float4 acc = make_float4(0.f, 0.f, 0.f, 0.f);
#pragma unroll
    for (int k = 0; k < 2; k++) {
        int f = 2 * t + k;
        int pos = g_assign_pos[f];
        if (pos >= 0) {
            int e = g_flat_sel[f];
            float s = g_flat_scale[f];
            float4 v = ((const float4*)(g_ybuf + (size_t)(e * CAP + pos) * HID))[tid];
            acc.x += s * v.x; acc.y += s * v.y; acc.z += s * v.z; acc.w += s * v.w;
        }
    }
    ((float4*)(out + (size_t)t * HID))[tid] = acc;
}

// ---------------- launch ----------------
extern "C" void kernel_launch(void* const* d_in, const int* in_sizes, int n_in,
                              void* d_out, int out_size) {
    const float* hidden = (const float*)d_in[0];
    const float* logits = (const float*)d_in[1];
    const float* w31    = (const float*)d_in[2];
    const float* w2     = (const float*)d_in[3];
    float* out = (float*)d_out;

    routing_kernel<<<1, 512>>>(logits);
    gather_split<<<NEXP * CAP, 256>>>(hidden);
    split_kernel<<<4096, 256>>>(w31, 0, NEXP * 2 * IDIM * HID / 4);
    split_kernel<<<4096, 256>>>(w2, 1, NEXP * HID * IDIM / 4);
    hmma_gemm<2 * IDIM, HID, true><<<dim3(32, 6, NEXP), 256>>>();
    act_kernel<<<(NEXP * CAP * IDIM / 4) / 256, 256>>>();
    hmma_gemm<HID, IDIM, false><<<dim3(8, 6, NEXP), 256>>>();
    scatter_kernel<<<NTOK, 256>>>(out);
}

// round 8
// speedup vs baseline: 2.1627x; 1.2016x over previous
#include <cuda_runtime.h>
#include <cuda_bf16.h>
#include <cstdint>

#define NTOK  4096
#define HID   1024
#define NEXP  16
#define IDIM  2048
#define CAP   768
#define NFLAT (NTOK * 2)

// ---------------- device scratch (no allocs allowed) ----------------
__device__ int   g_flat_sel[NFLAT];
__device__ float g_flat_scale[NFLAT];
__device__ int   g_assign_pos[NFLAT];
__device__ int   g_expert_count[NEXP];
__device__ int   g_expert_tok[NEXP * CAP];

__device__ __align__(256) __nv_bfloat16 g_xh[(size_t)NEXP * CAP * HID];
__device__ __align__(256) __nv_bfloat16 g_xl[(size_t)NEXP * CAP * HID];
__device__ __align__(256) __nv_bfloat16 g_ih[(size_t)NEXP * CAP * IDIM];
__device__ __align__(256) __nv_bfloat16 g_il[(size_t)NEXP * CAP * IDIM];
__device__ __align__(256) __nv_bfloat16 g_w31h[(size_t)NEXP * 2 * IDIM * HID];
__device__ __align__(256) __nv_bfloat16 g_w31l[(size_t)NEXP * 2 * IDIM * HID];
__device__ __align__(256) __nv_bfloat16 g_w2h[(size_t)NEXP * HID * IDIM];
__device__ __align__(256) __nv_bfloat16 g_w2l[(size_t)NEXP * HID * IDIM];
__device__ __align__(256) float g_hbuf[(size_t)NEXP * CAP * 2 * IDIM];
__device__ __align__(256) float g_ybuf[(size_t)NEXP * CAP * HID];

// ---------------- helpers ----------------
__device__ __forceinline__ uint32_t smem_u32(const void* p) {
    uint32_t a;
    asm("{ .reg .u64 t; cvta.to.shared.u64 t, %1; cvt.u32.u64 %0, t; }" : "=r"(a) : "l"(p));
    return a;
}
__device__ __forceinline__ void cpa16(uint32_t s, const void* g) {
    asm volatile("cp.async.cg.shared.global [%0], [%1], 16;" :: "r"(s), "l"(g) : "memory");
}
__device__ __forceinline__ void ldsm4(uint32_t& r0, uint32_t& r1, uint32_t& r2, uint32_t& r3,
                                      uint32_t addr) {
    asm volatile("ldmatrix.sync.aligned.m8n8.x4.shared.b16 {%0,%1,%2,%3}, [%4];"
                 : "=r"(r0), "=r"(r1), "=r"(r2), "=r"(r3) : "r"(addr));
}
__device__ __forceinline__ void mma16816(float* c, const uint32_t* a, const uint32_t* b) {
    asm volatile(
        "mma.sync.aligned.m16n8k16.row.col.f32.bf16.bf16.f32 "
        "{%0,%1,%2,%3}, {%4,%5,%6,%7}, {%8,%9}, {%0,%1,%2,%3};"
        : "+f"(c[0]), "+f"(c[1]), "+f"(c[2]), "+f"(c[3])
        : "r"(a[0]), "r"(a[1]), "r"(a[2]), "r"(a[3]), "r"(b[0]), "r"(b[1]));
}
__device__ __forceinline__ uint32_t pack2(__nv_bfloat16 a, __nv_bfloat16 b) {
    __nv_bfloat162 t(a, b);
    return *reinterpret_cast<uint32_t*>(&t);
}
// padded smem tile: 128 rows x 32 bf16 (64B data), row stride 80B -> conflict-free
#define ROW_B 80
#define TILE_B (128 * ROW_B)          // 10240 bytes per operand tile
#define STAGE_B (2 * TILE_B)          // 20480 (A + B)
#define NSTAGE 3
#define SMEM_BYTES (NSTAGE * STAGE_B) // 61440

// ---------------- routing: softmax top-2 + capacity positions ----------------
__global__ void routing_kernel(const float* __restrict__ logits) {
    __shared__ unsigned char sh_sel[NFLAT];
    const int tid = threadIdx.x;  // 512 threads = 16 warps

    for (int t = tid; t < NTOK; t += 512) {
        const float* l = logits + t * NEXP;
        float l1 = -1e30f, l2 = -1e30f;
        int i1 = 0, i2 = 0;
#pragma unroll
        for (int j = 0; j < NEXP; j++) {
            float v = l[j];
            if (v > l1)      { l2 = l1; i2 = i1; l1 = v; i1 = j; }
            else if (v > l2) { l2 = v; i2 = j; }
        }
        float e2 = __expf(l2 - l1);
        float s1 = 1.f / (1.f + e2);
        g_flat_sel[2 * t]     = i1;
        g_flat_sel[2 * t + 1] = i2;
        g_flat_scale[2 * t]     = s1;
        g_flat_scale[2 * t + 1] = 1.f - s1;
        sh_sel[2 * t]     = (unsigned char)i1;
        sh_sel[2 * t + 1] = (unsigned char)i2;
    }
    __syncthreads();

    const int w = tid >> 5, lane = tid & 31;
    int base = 0;
    for (int c = 0; c < NFLAT; c += 32) {
        int s = sh_sel[c + lane];
        unsigned m = __ballot_sync(0xffffffffu, s == w);
        if (s == w) {
            int pos = base + __popc(m & ((1u << lane) - 1u));
            g_assign_pos[c + lane] = (pos < CAP) ? pos : -1;
            if (pos < CAP) g_expert_tok[w * CAP + pos] = (c + lane) >> 1;
        }
        base += __popc(m);
    }
    if (lane == 0) g_expert_count[w] = base < CAP ? base : CAP;
}

// ---------------- weight split: f32 -> bf16 hi + bf16 lo ----------------
// Destination __device__ arrays resolved in DEVICE code (host symbol = R4-R6 bug).
__global__ void split_kernel(const float* __restrict__ src, int which, int n4) {
    __nv_bfloat16* hi = which ? g_w2h : g_w31h;
    __nv_bfloat16* lo = which ? g_w2l : g_w31l;
    int stride = gridDim.x * blockDim.x;
    for (int i = blockIdx.x * blockDim.x + threadIdx.x; i < n4; i += stride) {
        float4 v = ((const float4*)src)[i];
        __nv_bfloat16 h0 = __float2bfloat16_rn(v.x), h1 = __float2bfloat16_rn(v.y);
        __nv_bfloat16 h2 = __float2bfloat16_rn(v.z), h3 = __float2bfloat16_rn(v.w);
        ((uint2*)hi)[i] = make_uint2(pack2(h0, h1), pack2(h2, h3));
        ((uint2*)lo)[i] = make_uint2(
            pack2(__float2bfloat16_rn(v.x - __bfloat162float(h0)),
                  __float2bfloat16_rn(v.y - __bfloat162float(h1))),
            pack2(__float2bfloat16_rn(v.z - __bfloat162float(h2)),
                  __float2bfloat16_rn(v.w - __bfloat162float(h3))));
    }
}

// ---------------- gather rows into contiguous split-bf16 buffer ----------------
__global__ void gather_split(const float* __restrict__ hidden) {
    const int row = blockIdx.x;            // [0, NEXP*CAP)
    const int e = row / CAP, p = row % CAP;
    const int t = threadIdx.x;             // 256, one float4 each
    float4 v = make_float4(0.f, 0.f, 0.f, 0.f);
    if (p < g_expert_count[e]) {
        int tok = g_expert_tok[row];
        v = ((const float4*)(hidden + (size_t)tok * HID))[t];
    }
    __nv_bfloat16 h0 = __float2bfloat16_rn(v.x), h1 = __float2bfloat16_rn(v.y);
    __nv_bfloat16 h2 = __float2bfloat16_rn(v.z), h3 = __float2bfloat16_rn(v.w);
    *(uint2*)(g_xh + (size_t)row * HID + t * 4) = make_uint2(pack2(h0, h1), pack2(h2, h3));
    *(uint2*)(g_xl + (size_t)row * HID + t * 4) = make_uint2(
        pack2(__float2bfloat16_rn(v.x - __bfloat162float(h0)),
              __float2bfloat16_rn(v.y - __bfloat162float(h1))),
        pack2(__float2bfloat16_rn(v.z - __bfloat162float(h2)),
              __float2bfloat16_rn(v.w - __bfloat162float(h3))));
}

// ---------------- bf16 HMMA GEMM, virtual tripled-K, cp.async + ldmatrix ----------------
// C[row][n] = Ah*Bh + Al*Bh + Ah*Bl  (fp32 emulation via 3 virtual K segments)
// CTA tile 128x128, BK=32 bf16, 3-stage cp.async pipeline, 8 warps (4m x 2n).
template<int NTOT, int K, bool FIRST>
__global__ __launch_bounds__(256, 2) void hmma_gemm() {
    const int e = blockIdx.z;
    if ((int)(blockIdx.y * 128) >= g_expert_count[e]) return;

    extern __shared__ __align__(128) char smem[];
    const uint32_t sb = smem_u32(smem);

    const size_t aoffg = ((size_t)e * CAP + (size_t)blockIdx.y * 128) * K;
    const __nv_bfloat16* Ah = (FIRST ? g_xh : g_ih) + aoffg;
    const __nv_bfloat16* Al = (FIRST ? g_xl : g_il) + aoffg;
    const size_t boffg = ((size_t)e * NTOT + (size_t)blockIdx.x * 128) * K;
    const __nv_bfloat16* Bh = (FIRST ? g_w31h : g_w2h) + boffg;
    const __nv_bfloat16* Bl = (FIRST ? g_w31l : g_w2l) + boffg;
    float* C = (FIRST ? g_hbuf : g_ybuf)
        + ((size_t)e * CAP + (size_t)blockIdx.y * 128) * NTOT + (size_t)blockIdx.x * 128;

    const int tid = threadIdx.x, lane = tid & 31, warp = tid >> 5;
    const int wm = (warp & 3) * 32, wn = (warp >> 2) * 64;

    // cp.async load map: rows (tid>>2), (tid>>2)+64, 16B chunk (tid&3)
    const int lrow0 = tid >> 2, lc0 = tid & 3;
    const int lrow1 = lrow0 + 64;
    const uint32_t s0 = (uint32_t)(lrow0 * ROW_B + lc0 * 16);
    const uint32_t s1 = (uint32_t)(lrow1 * ROW_B + lc0 * 16);
    const size_t ga0 = (size_t)lrow0 * K + lc0 * 8;
    const size_t ga1 = (size_t)lrow1 * K + lc0 * 8;

    // ldmatrix per-lane offsets (same coordinates as the verified vanilla version)
    uint32_t aoff[2][2], boff[4][2];
    {
        const int am = lane & 15, ah = lane >> 4;
        const int mt = lane >> 3;
        const int bn = ((mt >> 1) << 3) + (lane & 7), bh = mt & 1;
#pragma unroll
        for (int i = 0; i < 2; i++)
#pragma unroll
            for (int kk = 0; kk < 2; kk++)
                aoff[i][kk] = (uint32_t)((wm + i * 16 + am) * ROW_B + (kk * 2 + ah) * 16);
#pragma unroll
        for (int j = 0; j < 4; j++)
#pragma unroll
            for (int kk = 0; kk < 2; kk++)
                boff[j][kk] = (uint32_t)((wn + j * 16 + bn) * ROW_B + (kk * 2 + bh) * 16);
    }

    float acc[2][8][4];
#pragma unroll
    for (int i = 0; i < 2; i++)
#pragma unroll
        for (int j = 0; j < 8; j++)
#pragma unroll
            for (int q = 0; q < 4; q++) acc[i][j][q] = 0.f;

    constexpr int NK = 3 * K / 32;

    auto load_stage = [&](int kt) {
        const int k0 = kt * 32;
        const __nv_bfloat16 *As, *Bs;
        int kl;
        if (k0 < K)          { As = Ah; Bs = Bh; kl = k0; }
        else if (k0 < 2 * K) { As = Al; Bs = Bh; kl = k0 - K; }
        else                 { As = Ah; Bs = Bl; kl = k0 - 2 * K; }
        const uint32_t sa = sb + (kt % NSTAGE) * STAGE_B, sbf = sa + TILE_B;
        cpa16(sa + s0, As + ga0 + kl);
        cpa16(sa + s1, As + ga1 + kl);
        cpa16(sbf + s0, Bs + ga0 + kl);
        cpa16(sbf + s1, Bs + ga1 + kl);
    };

    load_stage(0);
    asm volatile("cp.async.commit_group;" ::: "memory");
    load_stage(1);
    asm volatile("cp.async.commit_group;" ::: "memory");

    for (int kt = 0; kt < NK; kt++) {
        asm volatile("cp.async.wait_group 1;" ::: "memory");
        __syncthreads();
        // prefetch stage kt+2 into the buffer consumed at kt-1
        if (kt + 2 < NK) load_stage(kt + 2);
        asm volatile("cp.async.commit_group;" ::: "memory");

        const uint32_t sa = sb + (kt % NSTAGE) * STAGE_B, sbf = sa + TILE_B;
#pragma unroll
        for (int kk = 0; kk < 2; kk++) {
            uint32_t aF[2][4], bF[8][2];
            ldsm4(aF[0][0], aF[0][1], aF[0][2], aF[0][3], sa + aoff[0][kk]);
            ldsm4(aF[1][0], aF[1][1], aF[1][2], aF[1][3], sa + aoff[1][kk]);
#pragma unroll
            for (int j = 0; j < 4; j++)
                ldsm4(bF[2 * j][0], bF[2 * j][1], bF[2 * j + 1][0], bF[2 * j + 1][1],
                      sbf + boff[j][kk]);
#pragma unroll
            for (int i = 0; i < 2; i++)
#pragma unroll
                for (int j = 0; j < 8; j++)
                    mma16816(acc[i][j], aF[i], bF[j]);
        }
    }

    // epilogue: standard m16n8 C layout, f32 stores
    const int er = lane >> 2, ec = (lane & 3) * 2;
#pragma unroll
    for (int i = 0; i < 2; i++) {
#pragma unroll
        for (int j = 0; j < 8; j++) {
            float* p0 = C + (size_t)(wm + i * 16 + er) * NTOT + wn + j * 8 + ec;
            float* p1 = p0 + (size_t)8 * NTOT;
            *(float2*)p0 = make_float2(acc[i][j][0], acc[i][j][1]);
            *(float2*)p1 = make_float2(acc[i][j][2], acc[i][j][3]);
        }
    }
}

// ---------------- activation: inter = g3 * silu(g1), split to bf16 hi/lo ----------------
__global__ void act_kernel() {
    size_t idx4 = (size_t)blockIdx.x * 256 + threadIdx.x;   // float4 groups
    size_t row = idx4 >> 9;            // IDIM/4 = 512 groups per row
    int c4 = (int)(idx4 & 511);
    const float* hrow = g_hbuf + row * (2 * IDIM);
    float4 g3 = *(const float4*)(hrow + c4 * 4);
    float4 g1 = *(const float4*)(hrow + IDIM + c4 * 4);
    float4 o;
    o.x = g3.x * (g1.x / (1.f + __expf(-g1.x)));
    o.y = g3.y * (g1.y / (1.f + __expf(-g1.y)));
    o.z = g3.z * (g1.z / (1.f + __expf(-g1.z)));
    o.w = g3.w * (g1.w / (1.f + __expf(-g1.w)));
    __nv_bfloat16 h0 = __float2bfloat16_rn(o.x), h1 = __float2bfloat16_rn(o.y);
    __nv_bfloat16 h2 = __float2bfloat16_rn(o.z), h3 = __float2bfloat16_rn(o.w);
    *(uint2*)(g_ih + row * IDIM + c4 * 4) = make_uint2(pack2(h0, h1), pack2(h2, h3));
    *(uint2*)(g_il + row * IDIM + c4 * 4) = make_uint2(
        pack2(__float2bfloat16_rn(o.x - __bfloat162float(h0)),
              __float2bfloat16_rn(o.y - __bfloat162float(h1))),
        pack2(__float2bfloat16_rn(o.z - __bfloat162float(h2)),
              __float2bfloat16_rn(o.w - __bfloat162float(h3))));
}

// ---------------- scatter back: out[t] = sum_k scale * y[e, pos] ----------------
__global__ void scatter_kernel(float* __restrict__ out) {
    const int t = blockIdx.x;
    const int tid = threadIdx.x;  // 256, one float4 each
    float4 acc = make_float4(0.f, 0.f, 0.f, 0.f);
#pragma unroll
    for (int k = 0; k < 2; k++) {
        int f = 2 * t + k;
        int pos = g_assign_pos[f];
        if (pos >= 0) {
            int e = g_flat_sel[f];
            float s = g_flat_scale[f];
            float4 v = ((const float4*)(g_ybuf + (size_t)(e * CAP + pos) * HID))[tid];
            acc.x += s * v.x; acc.y += s * v.y; acc.z += s * v.z; acc.w += s * v.w;
        }
    }
    ((float4*)(out + (size_t)t * HID))[tid] = acc;
}

// ---------------- launch ----------------
extern "C" void kernel_launch(void* const* d_in, const int* in_sizes, int n_in,
                              void* d_out, int out_size) {
    const float* hidden = (const float*)d_in[0];
    const float* logits = (const float*)d_in[1];
    const float* w31    = (const float*)d_in[2];
    const float* w2     = (const float*)d_in[3];
    float* out = (float*)d_out;

    static int smem_set = 0;
    if (!smem_set) {
        cudaFuncSetAttribute(hmma_gemm<2 * IDIM, HID, true>,
                             cudaFuncAttributeMaxDynamicSharedMemorySize, SMEM_BYTES);
        cudaFuncSetAttribute(hmma_gemm<HID, IDIM, false>,
                             cudaFuncAttributeMaxDynamicSharedMemorySize, SMEM_BYTES);
        smem_set = 1;
    }

    routing_kernel<<<1, 512>>>(logits);
    gather_split<<<NEXP * CAP, 256>>>(hidden);
    split_kernel<<<4096, 256>>>(w31, 0, NEXP * 2 * IDIM * HID / 4);
    split_kernel<<<4096, 256>>>(w2, 1, NEXP * HID * IDIM / 4);
    hmma_gemm<2 * IDIM, HID, true><<<dim3(32, 6, NEXP), 256, SMEM_BYTES>>>();
    act_kernel<<<(NEXP * CAP * IDIM / 4) / 256, 256>>>();
    hmma_gemm<HID, IDIM, false><<<dim3(8, 6, NEXP), 256, SMEM_BYTES>>>();
    scatter_kernel<<<NTOK, 256>>>(out);
}

// round 9
// speedup vs baseline: 3.4306x; 1.5863x over previous
#include <cuda_runtime.h>
#include <cuda_fp16.h>
#include <cstdint>

#define NTOK  4096
#define HID   1024
#define NEXP  16
#define IDIM  2048
#define CAP   768
#define NFLAT (NTOK * 2)

// ---------------- device scratch (no allocs allowed) ----------------
__device__ int   g_flat_sel[NFLAT];
__device__ float g_flat_scale[NFLAT];
__device__ int   g_assign_pos[NFLAT];
__device__ int   g_expert_count[NEXP];
__device__ int   g_expert_tok[NEXP * CAP];

__device__ __align__(256) __half g_xh[(size_t)NEXP * CAP * HID];          // A1 hi
__device__ __align__(256) __half g_xl[(size_t)NEXP * CAP * HID];          // A1 lo
__device__ __align__(256) __half g_ih[(size_t)NEXP * CAP * IDIM];         // A2 hi
__device__ __align__(256) __half g_il[(size_t)NEXP * CAP * IDIM];         // A2 lo
__device__ __align__(256) __half g_w31[(size_t)NEXP * 2 * IDIM * HID];    // B1 fp16
__device__ __align__(256) __half g_w2[(size_t)NEXP * HID * IDIM];         // B2 fp16
__device__ __align__(256) float g_hbuf[(size_t)NEXP * CAP * 2 * IDIM];
__device__ __align__(256) float g_ybuf[(size_t)NEXP * CAP * HID];

// ---------------- helpers ----------------
__device__ __forceinline__ uint32_t smem_u32(const void* p) {
    uint32_t a;
    asm("{ .reg .u64 t; cvta.to.shared.u64 t, %1; cvt.u32.u64 %0, t; }" : "=r"(a) : "l"(p));
    return a;
}
__device__ __forceinline__ void cpa16(uint32_t s, const void* g) {
    asm volatile("cp.async.cg.shared.global [%0], [%1], 16;" :: "r"(s), "l"(g) : "memory");
}
__device__ __forceinline__ void ldsm4(uint32_t& r0, uint32_t& r1, uint32_t& r2, uint32_t& r3,
                                      uint32_t addr) {
    asm volatile("ldmatrix.sync.aligned.m8n8.x4.shared.b16 {%0,%1,%2,%3}, [%4];"
                 : "=r"(r0), "=r"(r1), "=r"(r2), "=r"(r3) : "r"(addr));
}
__device__ __forceinline__ void mma16816(float* c, const uint32_t* a, const uint32_t* b) {
    asm volatile(
        "mma.sync.aligned.m16n8k16.row.col.f32.f16.f16.f32 "
        "{%0,%1,%2,%3}, {%4,%5,%6,%7}, {%8,%9}, {%0,%1,%2,%3};"
        : "+f"(c[0]), "+f"(c[1]), "+f"(c[2]), "+f"(c[3])
        : "r"(a[0]), "r"(a[1]), "r"(a[2]), "r"(a[3]), "r"(b[0]), "r"(b[1]));
}
__device__ __forceinline__ uint32_t pack2h(__half a, __half b) {
    __half2 t(a, b);
    return *reinterpret_cast<uint32_t*>(&t);
}
// padded smem tile: 128 rows x 32 fp16 (64B data), row stride 80B -> conflict-free
#define ROW_B 80
#define TILE_B (128 * ROW_B)          // 10240 bytes per operand tile
#define STAGE_B (3 * TILE_B)          // 30720: Ah | Al | B
#define NSTAGE 3
#define SMEM_BYTES (NSTAGE * STAGE_B) // 92160

// ---------------- routing: softmax top-2 + capacity positions ----------------
__global__ void routing_kernel(const float* __restrict__ logits) {
    __shared__ unsigned char sh_sel[NFLAT];
    const int tid = threadIdx.x;  // 512 threads = 16 warps

    for (int t = tid; t < NTOK; t += 512) {
        const float* l = logits + t * NEXP;
        float l1 = -1e30f, l2 = -1e30f;
        int i1 = 0, i2 = 0;
#pragma unroll
        for (int j = 0; j < NEXP; j++) {
            float v = l[j];
            if (v > l1)      { l2 = l1; i2 = i1; l1 = v; i1 = j; }
            else if (v > l2) { l2 = v; i2 = j; }
        }
        float e2 = __expf(l2 - l1);
        float s1 = 1.f / (1.f + e2);
        g_flat_sel[2 * t]     = i1;
        g_flat_sel[2 * t + 1] = i2;
        g_flat_scale[2 * t]     = s1;
        g_flat_scale[2 * t + 1] = 1.f - s1;
        sh_sel[2 * t]     = (unsigned char)i1;
        sh_sel[2 * t + 1] = (unsigned char)i2;
    }
    __syncthreads();

    const int w = tid >> 5, lane = tid & 31;
    int base = 0;
    for (int c = 0; c < NFLAT; c += 32) {
        int s = sh_sel[c + lane];
        unsigned m = __ballot_sync(0xffffffffu, s == w);
        if (s == w) {
            int pos = base + __popc(m & ((1u << lane) - 1u));
            g_assign_pos[c + lane] = (pos < CAP) ? pos : -1;
            if (pos < CAP) g_expert_tok[w * CAP + pos] = (c + lane) >> 1;
        }
        base += __popc(m);
    }
    if (lane == 0) g_expert_count[w] = base < CAP ? base : CAP;
}

// ---------------- weight convert: f32 -> fp16 (B side needs no lo term) ----------------
// Destination __device__ arrays resolved in DEVICE code (host symbol = R4-R6 bug).
__global__ void wcvt_kernel(const float* __restrict__ src, int which, int n4) {
    __half* dst = which ? g_w2 : g_w31;
    int stride = gridDim.x * blockDim.x;
    for (int i = blockIdx.x * blockDim.x + threadIdx.x; i < n4; i += stride) {
        float4 v = ((const float4*)src)[i];
        ((uint2*)dst)[i] = make_uint2(
            pack2h(__float2half_rn(v.x), __float2half_rn(v.y)),
            pack2h(__float2half_rn(v.z), __float2half_rn(v.w)));
    }
}

// ---------------- gather rows into contiguous split-fp16 buffer ----------------
__global__ void gather_split(const float* __restrict__ hidden) {
    const int row = blockIdx.x;            // [0, NEXP*CAP)
    const int e = row / CAP, p = row % CAP;
    const int t = threadIdx.x;             // 256, one float4 each
    float4 v = make_float4(0.f, 0.f, 0.f, 0.f);
    if (p < g_expert_count[e]) {
        int tok = g_expert_tok[row];
        v = ((const float4*)(hidden + (size_t)tok * HID))[t];
    }
    __half h0 = __float2half_rn(v.x), h1 = __float2half_rn(v.y);
    __half h2 = __float2half_rn(v.z), h3 = __float2half_rn(v.w);
    *(uint2*)(g_xh + (size_t)row * HID + t * 4) = make_uint2(pack2h(h0, h1), pack2h(h2, h3));
    *(uint2*)(g_xl + (size_t)row * HID + t * 4) = make_uint2(
        pack2h(__float2half_rn(v.x - __half2float(h0)),
               __float2half_rn(v.y - __half2float(h1))),
        pack2h(__float2half_rn(v.z - __half2float(h2)),
               __float2half_rn(v.w - __half2float(h3))));
}

// ---------------- fp16 HMMA GEMM, 2-term A-split: C = (Ah + Al) * B ----------------
// CTA tile 128x128, BK=32 real-k fp16, 3-stage cp.async; per chunk B fragments
// are loaded once and reused for the Ah and Al passes (halves LDSM pressure).
template<int NTOT, int K, bool FIRST>
__global__ __launch_bounds__(256, 2) void hmma_gemm() {
    const int e = blockIdx.z;
    if ((int)(blockIdx.y * 128) >= g_expert_count[e]) return;

    extern __shared__ __align__(128) char smem[];
    const uint32_t sb = smem_u32(smem);

    const size_t aoffg = ((size_t)e * CAP + (size_t)blockIdx.y * 128) * K;
    const __half* Ah = (FIRST ? g_xh : g_ih) + aoffg;
    const __half* Al = (FIRST ? g_xl : g_il) + aoffg;
    const size_t boffg = ((size_t)e * NTOT + (size_t)blockIdx.x * 128) * K;
    const __half* B = (FIRST ? g_w31 : g_w2) + boffg;
    float* C = (FIRST ? g_hbuf : g_ybuf)
        + ((size_t)e * CAP + (size_t)blockIdx.y * 128) * NTOT + (size_t)blockIdx.x * 128;

    const int tid = threadIdx.x, lane = tid & 31, warp = tid >> 5;
    const int wm = (warp & 3) * 32, wn = (warp >> 2) * 64;

    // cp.async load map: rows (tid>>2), (tid>>2)+64, 16B chunk (tid&3)
    const int lrow0 = tid >> 2, lc0 = tid & 3;
    const int lrow1 = lrow0 + 64;
    const uint32_t s0 = (uint32_t)(lrow0 * ROW_B + lc0 * 16);
    const uint32_t s1 = (uint32_t)(lrow1 * ROW_B + lc0 * 16);
    const size_t ga0 = (size_t)lrow0 * K + lc0 * 8;
    const size_t ga1 = (size_t)lrow1 * K + lc0 * 8;

    // ldmatrix per-lane offsets (verified coordinates from R7/R8)
    uint32_t aoff[2][2], boff[4][2];
    {
        const int am = lane & 15, ah = lane >> 4;
        const int mt = lane >> 3;
        const int bn = ((mt >> 1) << 3) + (lane & 7), bh = mt & 1;
#pragma unroll
        for (int i = 0; i < 2; i++)
#pragma unroll
            for (int kk = 0; kk < 2; kk++)
                aoff[i][kk] = (uint32_t)((wm + i * 16 + am) * ROW_B + (kk * 2 + ah) * 16);
#pragma unroll
        for (int j = 0; j < 4; j++)
#pragma unroll
            for (int kk = 0; kk < 2; kk++)
                boff[j][kk] = (uint32_t)((wn + j * 16 + bn) * ROW_B + (kk * 2 + bh) * 16);
    }

    float acc[2][8][4];
#pragma unroll
    for (int i = 0; i < 2; i++)
#pragma unroll
        for (int j = 0; j < 8; j++)
#pragma unroll
            for (int q = 0; q < 4; q++) acc[i][j][q] = 0.f;

    constexpr int NK = K / 32;

    auto load_stage = [&](int kt) {
        const int kl = kt * 32;
        const uint32_t sa = sb + (kt % NSTAGE) * STAGE_B;
        cpa16(sa + s0, Ah + ga0 + kl);
        cpa16(sa + s1, Ah + ga1 + kl);
        cpa16(sa + TILE_B + s0, Al + ga0 + kl);
        cpa16(sa + TILE_B + s1, Al + ga1 + kl);
        cpa16(sa + 2 * TILE_B + s0, B + ga0 + kl);
        cpa16(sa + 2 * TILE_B + s1, B + ga1 + kl);
    };

    load_stage(0);
    asm volatile("cp.async.commit_group;" ::: "memory");
    load_stage(1);
    asm volatile("cp.async.commit_group;" ::: "memory");

    for (int kt = 0; kt < NK; kt++) {
        asm volatile("cp.async.wait_group 1;" ::: "memory");
        __syncthreads();
        if (kt + 2 < NK) load_stage(kt + 2);
        asm volatile("cp.async.commit_group;" ::: "memory");

        const uint32_t sa = sb + (kt % NSTAGE) * STAGE_B;
        const uint32_t sal = sa + TILE_B, sbf = sa + 2 * TILE_B;
#pragma unroll
        for (int kk = 0; kk < 2; kk++) {
            uint32_t aH[2][4], aL[2][4], bF[8][2];
            ldsm4(aH[0][0], aH[0][1], aH[0][2], aH[0][3], sa + aoff[0][kk]);
            ldsm4(aH[1][0], aH[1][1], aH[1][2], aH[1][3], sa + aoff[1][kk]);
            ldsm4(aL[0][0], aL[0][1], aL[0][2], aL[0][3], sal + aoff[0][kk]);
            ldsm4(aL[1][0], aL[1][1], aL[1][2], aL[1][3], sal + aoff[1][kk]);
#pragma unroll
            for (int j = 0; j < 4; j++)
                ldsm4(bF[2 * j][0], bF[2 * j][1], bF[2 * j + 1][0], bF[2 * j + 1][1],
                      sbf + boff[j][kk]);
#pragma unroll
            for (int i = 0; i < 2; i++)
#pragma unroll
                for (int j = 0; j < 8; j++) {
                    mma16816(acc[i][j], aH[i], bF[j]);
                    mma16816(acc[i][j], aL[i], bF[j]);
                }
        }
    }

    // epilogue: standard m16n8 C layout, f32 stores
    const int er = lane >> 2, ec = (lane & 3) * 2;
#pragma unroll
    for (int i = 0; i < 2; i++) {
#pragma unroll
        for (int j = 0; j < 8; j++) {
            float* p0 = C + (size_t)(wm + i * 16 + er) * NTOT + wn + j * 8 + ec;
            float* p1 = p0 + (size_t)8 * NTOT;
            *(float2*)p0 = make_float2(acc[i][j][0], acc[i][j][1]);
            *(float2*)p1 = make_float2(acc[i][j][2], acc[i][j][3]);
        }
    }
}

// ---------------- activation: inter = g3 * silu(g1), split to fp16 hi/lo ----------------
__global__ void act_kernel() {
    size_t idx4 = (size_t)blockIdx.x * 256 + threadIdx.x;   // float4 groups
    size_t row = idx4 >> 9;            // IDIM/4 = 512 groups per row
    int c4 = (int)(idx4 & 511);
    const float* hrow = g_hbuf + row * (2 * IDIM);
    float4 g3 = *(const float4*)(hrow + c4 * 4);
    float4 g1 = *(const float4*)(hrow + IDIM + c4 * 4);
    float4 o;
    o.x = g3.x * (g1.x / (1.f + __expf(-g1.x)));
    o.y = g3.y * (g1.y / (1.f + __expf(-g1.y)));
    o.z = g3.z * (g1.z / (1.f + __expf(-g1.z)));
    o.w = g3.w * (g1.w / (1.f + __expf(-g1.w)));
    __half h0 = __float2half_rn(o.x), h1 = __float2half_rn(o.y);
    __half h2 = __float2half_rn(o.z), h3 = __float2half_rn(o.w);
    *(uint2*)(g_ih + row * IDIM + c4 * 4) = make_uint2(pack2h(h0, h1), pack2h(h2, h3));
    *(uint2*)(g_il + row * IDIM + c4 * 4) = make_uint2(
        pack2h(__float2half_rn(o.x - __half2float(h0)),
               __float2half_rn(o.y - __half2float(h1))),
        pack2h(__float2half_rn(o.z - __half2float(h2)),
               __float2half_rn(o.w - __half2float(h3))));
}

// ---------------- scatter back: out[t] = sum_k scale * y[e, pos] ----------------
__global__ void scatter_kernel(float* __restrict__ out) {
    const int t = blockIdx.x;
    const int tid = threadIdx.x;  // 256, one float4 each
    float4 acc = make_float4(0.f, 0.f, 0.f, 0.f);
#pragma unroll
    for (int k = 0; k < 2; k++) {
        int f = 2 * t + k;
        int pos = g_assign_pos[f];
        if (pos >= 0) {
            int e = g_flat_sel[f];
            float s = g_flat_scale[f];
            float4 v = ((const float4*)(g_ybuf + (size_t)(e * CAP + pos) * HID))[tid];
            acc.x += s * v.x; acc.y += s * v.y; acc.z += s * v.z; acc.w += s * v.w;
        }
    }
    ((float4*)(out + (size_t)t * HID))[tid] = acc;
}

// ---------------- launch ----------------
extern "C" void kernel_launch(void* const* d_in, const int* in_sizes, int n_in,
                              void* d_out, int out_size) {
    const float* hidden = (const float*)d_in[0];
    const float* logits = (const float*)d_in[1];
    const float* w31    = (const float*)d_in[2];
    const float* w2     = (const float*)d_in[3];
    float* out = (float*)d_out;

    static int smem_set = 0;
    if (!smem_set) {
        cudaFuncSetAttribute(hmma_gemm<2 * IDIM, HID, true>,
                             cudaFuncAttributeMaxDynamicSharedMemorySize, SMEM_BYTES);
        cudaFuncSetAttribute(hmma_gemm<HID, IDIM, false>,
                             cudaFuncAttributeMaxDynamicSharedMemorySize, SMEM_BYTES);
        smem_set = 1;
    }

    routing_kernel<<<1, 512>>>(logits);
    gather_split<<<NEXP * CAP, 256>>>(hidden);
    wcvt_kernel<<<4096, 256>>>(w31, 0, NEXP * 2 * IDIM * HID / 4);
    wcvt_kernel<<<4096, 256>>>(w2, 1, NEXP * HID * IDIM / 4);
    hmma_gemm<2 * IDIM, HID, true><<<dim3(32, 6, NEXP), 256, SMEM_BYTES>>>();
    act_kernel<<<(NEXP * CAP * IDIM / 4) / 256, 256>>>();
    hmma_gemm<HID, IDIM, false><<<dim3(8, 6, NEXP), 256, SMEM_BYTES>>>();
    scatter_kernel<<<NTOK, 256>>>(out);
}

// round 10
// speedup vs baseline: 5.2852x; 1.5406x over previous
#include <cuda_runtime.h>
#include <cuda_fp16.h>
#include <cstdint>

#define NTOK  4096
#define HID   1024
#define NEXP  16
#define IDIM  2048
#define CAP   768
#define NFLAT (NTOK * 2)

// ---------------- device scratch (no allocs allowed) ----------------
__device__ int   g_flat_sel[NFLAT];
__device__ float g_flat_scale[NFLAT];
__device__ int   g_assign_pos[NFLAT];
__device__ int   g_expert_count[NEXP];
__device__ int   g_expert_tok[NEXP * CAP];

__device__ __align__(256) __half g_x1[(size_t)NEXP * CAP * HID];          // A1 fp16
__device__ __align__(256) __half g_i2[(size_t)NEXP * CAP * IDIM];         // A2 fp16
__device__ __align__(256) __half g_w31[(size_t)NEXP * 2 * IDIM * HID];    // B1 fp16
__device__ __align__(256) __half g_w2[(size_t)NEXP * HID * IDIM];         // B2 fp16
__device__ __align__(256) float g_hbuf[(size_t)NEXP * CAP * 2 * IDIM];
__device__ __align__(256) float g_ybuf[(size_t)NEXP * CAP * HID];

// ---------------- helpers ----------------
__device__ __forceinline__ uint32_t smem_u32(const void* p) {
    uint32_t a;
    asm("{ .reg .u64 t; cvta.to.shared.u64 t, %1; cvt.u32.u64 %0, t; }" : "=r"(a) : "l"(p));
    return a;
}
__device__ __forceinline__ void cpa16(uint32_t s, const void* g) {
    asm volatile("cp.async.cg.shared.global [%0], [%1], 16;" :: "r"(s), "l"(g) : "memory");
}
__device__ __forceinline__ void ldsm4(uint32_t& r0, uint32_t& r1, uint32_t& r2, uint32_t& r3,
                                      uint32_t addr) {
    asm volatile("ldmatrix.sync.aligned.m8n8.x4.shared.b16 {%0,%1,%2,%3}, [%4];"
                 : "=r"(r0), "=r"(r1), "=r"(r2), "=r"(r3) : "r"(addr));
}
__device__ __forceinline__ void mma16816(float* c, const uint32_t* a, const uint32_t* b) {
    asm volatile(
        "mma.sync.aligned.m16n8k16.row.col.f32.f16.f16.f32 "
        "{%0,%1,%2,%3}, {%4,%5,%6,%7}, {%8,%9}, {%0,%1,%2,%3};"
        : "+f"(c[0]), "+f"(c[1]), "+f"(c[2]), "+f"(c[3])
        : "r"(a[0]), "r"(a[1]), "r"(a[2]), "r"(a[3]), "r"(b[0]), "r"(b[1]));
}
__device__ __forceinline__ uint32_t pack2h(__half a, __half b) {
    __half2 t(a, b);
    return *reinterpret_cast<uint32_t*>(&t);
}
// padded smem tile: 128 rows x 32 fp16 (64B data), row stride 80B -> conflict-free
#define ROW_B 80
#define TILE_B (128 * ROW_B)          // 10240 bytes per operand tile
#define STAGE_B (2 * TILE_B)          // 20480: A | B
#define NSTAGE 3
#define SMEM_BYTES (NSTAGE * STAGE_B) // 61440

// ---------------- routing: softmax top-2 + capacity positions ----------------
__global__ void routing_kernel(const float* __restrict__ logits) {
    __shared__ unsigned char sh_sel[NFLAT];
    const int tid = threadIdx.x;  // 512 threads = 16 warps

    for (int t = tid; t < NTOK; t += 512) {
        const float* l = logits + t * NEXP;
        float l1 = -1e30f, l2 = -1e30f;
        int i1 = 0, i2 = 0;
#pragma unroll
        for (int j = 0; j < NEXP; j++) {
            float v = l[j];
            if (v > l1)      { l2 = l1; i2 = i1; l1 = v; i1 = j; }
            else if (v > l2) { l2 = v; i2 = j; }
        }
        float e2 = __expf(l2 - l1);
        float s1 = 1.f / (1.f + e2);
        g_flat_sel[2 * t]     = i1;
        g_flat_sel[2 * t + 1] = i2;
        g_flat_scale[2 * t]     = s1;
        g_flat_scale[2 * t + 1] = 1.f - s1;
        sh_sel[2 * t]     = (unsigned char)i1;
        sh_sel[2 * t + 1] = (unsigned char)i2;
    }
    __syncthreads();

    const int w = tid >> 5, lane = tid & 31;
    int base = 0;
    for (int c = 0; c < NFLAT; c += 32) {
        int s = sh_sel[c + lane];
        unsigned m = __ballot_sync(0xffffffffu, s == w);
        if (s == w) {
            int pos = base + __popc(m & ((1u << lane) - 1u));
            g_assign_pos[c + lane] = (pos < CAP) ? pos : -1;
            if (pos < CAP) g_expert_tok[w * CAP + pos] = (c + lane) >> 1;
        }
        base += __popc(m);
    }
    if (lane == 0) g_expert_count[w] = base < CAP ? base : CAP;
}

// ---------------- weight convert: f32 -> fp16 ----------------
// Destination __device__ arrays resolved in DEVICE code (host symbol = R4-R6 bug).
__global__ void wcvt_kernel(const float* __restrict__ src, int which, int n4) {
    __half* dst = which ? g_w2 : g_w31;
    int stride = gridDim.x * blockDim.x;
    for (int i = blockIdx.x * blockDim.x + threadIdx.x; i < n4; i += stride) {
        float4 v = ((const float4*)src)[i];
        ((uint2*)dst)[i] = make_uint2(
            pack2h(__float2half_rn(v.x), __float2half_rn(v.y)),
            pack2h(__float2half_rn(v.z), __float2half_rn(v.w)));
    }
}

// ---------------- gather rows into contiguous fp16 buffer ----------------
__global__ void gather_kernel(const float* __restrict__ hidden) {
    const int row = blockIdx.x;            // [0, NEXP*CAP)
    const int e = row / CAP, p = row % CAP;
    const int t = threadIdx.x;             // 256, one float4 each
    float4 v = make_float4(0.f, 0.f, 0.f, 0.f);
    if (p < g_expert_count[e]) {
        int tok = g_expert_tok[row];
        v = ((const float4*)(hidden + (size_t)tok * HID))[t];
    }
    *(uint2*)(g_x1 + (size_t)row * HID + t * 4) = make_uint2(
        pack2h(__float2half_rn(v.x), __float2half_rn(v.y)),
        pack2h(__float2half_rn(v.z), __float2half_rn(v.w)));
}

// ---------------- fp16 HMMA GEMM: C[row][n] = sum_k A[row][k] * B[n][k] ----------------
// CTA tile 128x128, BK=32 fp16, 3-stage cp.async pipeline, 8 warps (4m x 2n).
template<int NTOT, int K, bool FIRST>
__global__ __launch_bounds__(256, 2) void hmma_gemm() {
    const int e = blockIdx.z;
    if ((int)(blockIdx.y * 128) >= g_expert_count[e]) return;

    extern __shared__ __align__(128) char smem[];
    const uint32_t sb = smem_u32(smem);

    const __half* A = (FIRST ? g_x1 : g_i2)
        + ((size_t)e * CAP + (size_t)blockIdx.y * 128) * K;
    const __half* B = (FIRST ? g_w31 : g_w2)
        + ((size_t)e * NTOT + (size_t)blockIdx.x * 128) * K;
    float* C = (FIRST ? g_hbuf : g_ybuf)
        + ((size_t)e * CAP + (size_t)blockIdx.y * 128) * NTOT + (size_t)blockIdx.x * 128;

    const int tid = threadIdx.x, lane = tid & 31, warp = tid >> 5;
    const int wm = (warp & 3) * 32, wn = (warp >> 2) * 64;

    // cp.async load map: rows (tid>>2), (tid>>2)+64, 16B chunk (tid&3)
    const int lrow0 = tid >> 2, lc0 = tid & 3;
    const int lrow1 = lrow0 + 64;
    const uint32_t s0 = (uint32_t)(lrow0 * ROW_B + lc0 * 16);
    const uint32_t s1 = (uint32_t)(lrow1 * ROW_B + lc0 * 16);
    const size_t ga0 = (size_t)lrow0 * K + lc0 * 8;
    const size_t ga1 = (size_t)lrow1 * K + lc0 * 8;

    // ldmatrix per-lane offsets (verified coordinates from R7/R8/R9)
    uint32_t aoff[2][2], boff[4][2];
    {
        const int am = lane & 15, ah = lane >> 4;
        const int mt = lane >> 3;
        const int bn = ((mt >> 1) << 3) + (lane & 7), bh = mt & 1;
#pragma unroll
        for (int i = 0; i < 2; i++)
#pragma unroll
            for (int kk = 0; kk < 2; kk++)
                aoff[i][kk] = (uint32_t)((wm + i * 16 + am) * ROW_B + (kk * 2 + ah) * 16);
#pragma unroll
        for (int j = 0; j < 4; j++)
#pragma unroll
            for (int kk = 0; kk < 2; kk++)
                boff[j][kk] = (uint32_t)((wn + j * 16 + bn) * ROW_B + (kk * 2 + bh) * 16);
    }

    float acc[2][8][4];
#pragma unroll
    for (int i = 0; i < 2; i++)
#pragma unroll
        for (int j = 0; j < 8; j++)
#pragma unroll
            for (int q = 0; q < 4; q++) acc[i][j][q] = 0.f;

    constexpr int NK = K / 32;

    auto load_stage = [&](int kt) {
        const int kl = kt * 32;
        const uint32_t sa = sb + (kt % NSTAGE) * STAGE_B;
        cpa16(sa + s0, A + ga0 + kl);
        cpa16(sa + s1, A + ga1 + kl);
        cpa16(sa + TILE_B + s0, B + ga0 + kl);
        cpa16(sa + TILE_B + s1, B + ga1 + kl);
    };

    load_stage(0);
    asm volatile("cp.async.commit_group;" ::: "memory");
    load_stage(1);
    asm volatile("cp.async.commit_group;" ::: "memory");

    for (int kt = 0; kt < NK; kt++) {
        asm volatile("cp.async.wait_group 1;" ::: "memory");
        __syncthreads();
        if (kt + 2 < NK) load_stage(kt + 2);
        asm volatile("cp.async.commit_group;" ::: "memory");

        const uint32_t sa = sb + (kt % NSTAGE) * STAGE_B, sbf = sa + TILE_B;
#pragma unroll
        for (int kk = 0; kk < 2; kk++) {
            uint32_t aF[2][4], bF[8][2];
            ldsm4(aF[0][0], aF[0][1], aF[0][2], aF[0][3], sa + aoff[0][kk]);
            ldsm4(aF[1][0], aF[1][1], aF[1][2], aF[1][3], sa + aoff[1][kk]);
#pragma unroll
            for (int j = 0; j < 4; j++)
                ldsm4(bF[2 * j][0], bF[2 * j][1], bF[2 * j + 1][0], bF[2 * j + 1][1],
                      sbf + boff[j][kk]);
#pragma unroll
            for (int i = 0; i < 2; i++)
#pragma unroll
                for (int j = 0; j < 8; j++)
                    mma16816(acc[i][j], aF[i], bF[j]);
        }
    }

    // epilogue: standard m16n8 C layout, f32 stores
    const int er = lane >> 2, ec = (lane & 3) * 2;
#pragma unroll
    for (int i = 0; i < 2; i++) {
#pragma unroll
        for (int j = 0; j < 8; j++) {
            float* p0 = C + (size_t)(wm + i * 16 + er) * NTOT + wn + j * 8 + ec;
            float* p1 = p0 + (size_t)8 * NTOT;
            *(float2*)p0 = make_float2(acc[i][j][0], acc[i][j][1]);
            *(float2*)p1 = make_float2(acc[i][j][2], acc[i][j][3]);
        }
    }
}

// ---------------- activation: inter = g3 * silu(g1) -> fp16 ----------------
__global__ void act_kernel() {
    size_t idx4 = (size_t)blockIdx.x * 256 + threadIdx.x;   // float4 groups
    size_t row = idx4 >> 9;            // IDIM/4 = 512 groups per row
    int c4 = (int)(idx4 & 511);
    const float* hrow = g_hbuf + row * (2 * IDIM);
    float4 g3 = *(const float4*)(hrow + c4 * 4);
    float4 g1 = *(const float4*)(hrow + IDIM + c4 * 4);
    float4 o;
    o.x = g3.x * (g1.x / (1.f + __expf(-g1.x)));
    o.y = g3.y * (g1.y / (1.f + __expf(-g1.y)));
    o.z = g3.z * (g1.z / (1.f + __expf(-g1.z)));
    o.w = g3.w * (g1.w / (1.f + __expf(-g1.w)));
    *(uint2*)(g_i2 + row * IDIM + c4 * 4) = make_uint2(
        pack2h(__float2half_rn(o.x), __float2half_rn(o.y)),
        pack2h(__float2half_rn(o.z), __float2half_rn(o.w)));
}

// ---------------- scatter back: out[t] = sum_k scale * y[e, pos] ----------------
__global__ void scatter_kernel(float* __restrict__ out) {
    const int t = blockIdx.x;
    const int tid = threadIdx.x;  // 256, one float4 each
    float4 acc = make_float4(0.f, 0.f, 0.f, 0.f);
#pragma unroll
    for (int k = 0; k < 2; k++) {
        int f = 2 * t + k;
        int pos = g_assign_pos[f];
        if (pos >= 0) {
            int e = g_flat_sel[f];
            float s = g_flat_scale[f];
            float4 v = ((const float4*)(g_ybuf + (size_t)(e * CAP + pos) * HID))[tid];
            acc.x += s * v.x; acc.y += s * v.y; acc.z += s * v.z; acc.w += s * v.w;
        }
    }
    ((float4*)(out + (size_t)t * HID))[tid] = acc;
}

// ---------------- launch ----------------
extern "C" void kernel_launch(void* const* d_in, const int* in_sizes, int n_in,
                              void* d_out, int out_size) {
    const float* hidden = (const float*)d_in[0];
    const float* logits = (const float*)d_in[1];
    const float* w31    = (const float*)d_in[2];
    const float* w2     = (const float*)d_in[3];
    float* out = (float*)d_out;

    static int smem_set = 0;
    if (!smem_set) {
        cudaFuncSetAttribute(hmma_gemm<2 * IDIM, HID, true>,
                             cudaFuncAttributeMaxDynamicSharedMemorySize, SMEM_BYTES);
        cudaFuncSetAttribute(hmma_gemm<HID, IDIM, false>,
                             cudaFuncAttributeMaxDynamicSharedMemorySize, SMEM_BYTES);
        smem_set = 1;
    }

    routing_kernel<<<1, 512>>>(logits);
    gather_kernel<<<NEXP * CAP, 256>>>(hidden);
    wcvt_kernel<<<4096, 256>>>(w31, 0, NEXP * 2 * IDIM * HID / 4);
    wcvt_kernel<<<4096, 256>>>(w2, 1, NEXP * HID * IDIM / 4);
    hmma_gemm<2 * IDIM, HID, true><<<dim3(32, 6, NEXP), 256, SMEM_BYTES>>>();
    act_kernel<<<(NEXP * CAP * IDIM / 4) / 256, 256>>>();
    hmma_gemm<HID, IDIM, false><<<dim3(8, 6, NEXP), 256, SMEM_BYTES>>>();
    scatter_kernel<<<NTOK, 256>>>(out);
}